// round 13
// baseline (speedup 1.0000x reference)
#include <cuda_runtime.h>
#include <cuda_bf16.h>
#include <cstdint>

// ---------------------------------------------------------------------------
// B=2, N=512, D_IN=D_OUT=64, TEMP=100, POOL_K=0.5 -> kn=256
// ---------------------------------------------------------------------------
#define NB 2
#define NN 512
#define ND 64
#define KN 256
#define TEMP_INV (1.0f/100.0f)
#define BN_EPS 1e-5f
#define SELU_SCALE 1.0507009873554804934193349852946f
#define SELU_ALPHA 1.6732632423543772848170429916717f

__device__ float g_scores[NB*NN*NN];
__device__ float g_h[NB*NN*ND];
__device__ float g_aggp[NB*4*NN*ND];   // partial agg per k-segment
__device__ float g_sump[NB*4*NN];      // partial exp-sums per k-segment
__device__ float g_part[64*128];       // per-kH-block partial BN stats

__device__ __forceinline__ float tanh_approx(float x) {
    float r;
    asm("tanh.approx.f32 %0, %1;" : "=f"(r) : "f"(x));
    return r;
}
__device__ __forceinline__ uint32_t to_tf32(float f) {
    uint32_t u;
    asm("cvt.rna.tf32.f32 %0, %1;" : "=r"(u) : "f"(f));
    return u;
}
__device__ __forceinline__ void mma_tf32(float c[4], uint32_t a0, uint32_t a1,
                                         uint32_t a2, uint32_t a3,
                                         uint32_t b0, uint32_t b1) {
    asm("mma.sync.aligned.m16n8k8.row.col.f32.tf32.tf32.f32 "
        "{%0,%1,%2,%3}, {%4,%5,%6,%7}, {%8,%9}, {%0,%1,%2,%3};"
        : "+f"(c[0]), "+f"(c[1]), "+f"(c[2]), "+f"(c[3])
        : "r"(a0), "r"(a1), "r"(a2), "r"(a3), "r"(b0), "r"(b1));
}
__device__ __forceinline__ void mma_bf16(float c[4], const uint32_t a[4],
                                         uint32_t b0, uint32_t b1) {
    asm("mma.sync.aligned.m16n8k16.row.col.f32.bf16.bf16.f32 "
        "{%0,%1,%2,%3}, {%4,%5,%6,%7}, {%8,%9}, {%0,%1,%2,%3};"
        : "+f"(c[0]), "+f"(c[1]), "+f"(c[2]), "+f"(c[3])
        : "r"(a[0]), "r"(a[1]), "r"(a[2]), "r"(a[3]), "r"(b0), "r"(b1));
}
__device__ __forceinline__ void ldsm_x4(uint32_t r[4], uint32_t addr) {
    asm volatile("ldmatrix.sync.aligned.m8n8.x4.shared.b16 {%0,%1,%2,%3}, [%4];"
        : "=r"(r[0]), "=r"(r[1]), "=r"(r[2]), "=r"(r[3]) : "r"(addr));
}

// ---------------------------------------------------------------------------
// Phase 1 (bf16 tensor cores + ldmatrix + HOISTED B-fragments):
// scores upper triangle via symmetry. B (Wt) fragments are constant across
// all chunks of a row -> loaded once into 32 regs; per-chunk LDSM 12 -> 4.
// ---------------------------------------------------------------------------
__global__ __launch_bounds__(256) void kScores(
    const float* __restrict__ x,
    const float* __restrict__ apw,
    const float* __restrict__ apb,
    const float* __restrict__ awt)
{
    __shared__ __align__(16) __nv_bfloat16 Xs[64][72];  // [j][d]
    __shared__ __align__(16) __nv_bfloat16 Wt[64][72];  // [e][d]
    __shared__ float spart[2][64];
    __shared__ float xi_s[64], ab_s[64], aw_s[64];

    const int t = threadIdx.x;
    const int p = blockIdx.x;
    const int b = blockIdx.y;
    const float* xb = x + b * NN * ND;

    const int warp = t >> 5, lane = t & 31;
    const int jt = (warp & 3) * 16;
    const int eh = (warp >> 2) * 32;
    const int qr = lane >> 2, qc = lane & 3;

    if (t < 64) { ab_s[t] = apb[t]; aw_s[t] = awt[t]; }

    const uint32_t xsBase = (uint32_t)__cvta_generic_to_shared(&Xs[0][0]);
    const uint32_t wtBase = (uint32_t)__cvta_generic_to_shared(&Wt[0][0]);
    const uint32_t aAddr = xsBase + (jt + (lane & 15)) * 144 + (lane >> 4) * 16;
    const uint32_t bAddr1 = wtBase +
        (eh + (lane >> 4) * 8 + (lane & 7)) * 144 + ((lane >> 3) & 1) * 16;
    const uint32_t bAddr2 = bAddr1 + 16 * 144;

    #pragma unroll 1
    for (int r = 0; r < 2; r++) {
        const int i = r ? (NN - 1 - p) : p;
        __syncthreads();
        if (t < 64) xi_s[t] = xb[i * ND + t];
        __syncthreads();

        #pragma unroll
        for (int k = 0; k < 16; k++) {
            int idx = t + k * 256;
            int d = idx >> 6, e = idx & 63;
            Wt[e][d] = __float2bfloat16(xi_s[d] * apw[idx]);
        }
        __syncthreads();

        // hoisted B fragments (constant for this row)
        uint32_t bf1[4][4], bf2[4][4];
        #pragma unroll
        for (int ks = 0; ks < 4; ks++) {
            ldsm_x4(bf1[ks], bAddr1 + ks * 32);
            ldsm_x4(bf2[ks], bAddr2 + ks * 32);
        }

        for (int jc = i >> 6; jc < 8; jc++) {
            #pragma unroll
            for (int k = 0; k < 4; k++) {
                int v = t + k * 256;
                int j = v >> 4, d4 = v & 15;
                float4 f = *(const float4*)&xb[(jc * 64 + j) * ND + d4 * 4];
                __nv_bfloat162 lo = __float22bfloat162_rn(make_float2(f.x, f.y));
                __nv_bfloat162 hi = __float22bfloat162_rn(make_float2(f.z, f.w));
                uint2 u = { *(uint32_t*)&lo, *(uint32_t*)&hi };
                *(uint2*)&Xs[j][d4 * 4] = u;
            }
            __syncthreads();

            float acc[4][4] = {};
            #pragma unroll
            for (int ks = 0; ks < 4; ks++) {
                uint32_t a[4];
                ldsm_x4(a, aAddr + ks * 32);
                mma_bf16(acc[0], a, bf1[ks][0], bf1[ks][1]);
                mma_bf16(acc[1], a, bf1[ks][2], bf1[ks][3]);
                mma_bf16(acc[2], a, bf2[ks][0], bf2[ks][1]);
                mma_bf16(acc[3], a, bf2[ks][2], bf2[ks][3]);
            }

            float s0 = 0.f, s1 = 0.f;
            #pragma unroll
            for (int et = 0; et < 4; et++) {
                int e = eh + et * 8 + 2 * qc;
                s0 += aw_s[e]     * tanh_approx(acc[et][0] + ab_s[e]);
                s0 += aw_s[e + 1] * tanh_approx(acc[et][1] + ab_s[e + 1]);
                s1 += aw_s[e]     * tanh_approx(acc[et][2] + ab_s[e]);
                s1 += aw_s[e + 1] * tanh_approx(acc[et][3] + ab_s[e + 1]);
            }
            s0 += __shfl_xor_sync(0xffffffffu, s0, 1);
            s0 += __shfl_xor_sync(0xffffffffu, s0, 2);
            s1 += __shfl_xor_sync(0xffffffffu, s1, 1);
            s1 += __shfl_xor_sync(0xffffffffu, s1, 2);
            if (qc == 0) {
                spart[warp >> 2][jt + qr] = s0;
                spart[warp >> 2][jt + qr + 8] = s1;
            }
            __syncthreads();

            if (t < 64) {
                int j = jc * 64 + t;
                if (j >= i) {
                    float s = spart[0][t] + spart[1][t];
                    g_scores[(b * NN + i) * NN + j] = s;
                    g_scores[(b * NN + j) * NN + i] = s;
                }
            }
            __syncthreads();
        }
    }
}

// ---------------------------------------------------------------------------
// Phase 2a (k-split partial agg): grid (64, 4, NB) = 1024 blocks.
// Block = 8 rows x 128-k segment. Unnormalized exp (|s|/TEMP<=0.07, safe);
// partial agg via tf32 MMA (proven fragment pattern), partial sums to global.
// ---------------------------------------------------------------------------
__global__ __launch_bounds__(256) void kAggP(
    const float* __restrict__ x)
{
    __shared__ uint32_t As[16][68];                 // tf32 attn slice [m][k]
    __shared__ __align__(16) uint32_t Xs[64][72];   // tf32 X chunk [k][d]

    const int t = threadIdx.x;
    const int warp = t >> 5, lane = t & 31;
    const int qr = lane >> 2, qc = lane & 3;
    const int nt = warp;                 // d-tile nt*8..+8
    const int b = blockIdx.z;
    const int seg = blockIdx.y;          // k segment: rows seg*128..+127
    const int i0 = blockIdx.x * 8;
    const float* xb = x + b * NN * ND;

    // zero A-rows 8..15
    for (int idx = t; idx < 8 * 64; idx += 256)
        As[8 + (idx >> 6)][idx & 63] = 0;

    // unnormalized exp of this row's k-slice; warp owns row i0+warp
    float ev[4];
    {
        const float* srow = g_scores + (b * NN + i0 + warp) * NN + seg * 128;
        float sum = 0.f;
        #pragma unroll
        for (int q = 0; q < 4; q++) {
            ev[q] = __expf(srow[q * 32 + lane] * TEMP_INV);
            sum += ev[q];
        }
        #pragma unroll
        for (int o = 16; o > 0; o >>= 1)
            sum += __shfl_xor_sync(0xffffffffu, sum, o);
        if (lane == 0)
            g_sump[(b * 4 + seg) * NN + i0 + warp] = sum;
    }

    float acc[4] = {};
    #pragma unroll
    for (int c = 0; c < 2; c++) {
        __syncthreads();   // zeros visible (c=0) / prev chunk consumed (c=1)
        As[warp][lane]      = to_tf32(ev[2 * c]);
        As[warp][32 + lane] = to_tf32(ev[2 * c + 1]);
        const int k0row = seg * 128 + c * 64;
        #pragma unroll
        for (int k = 0; k < 4; k++) {
            int v = t + k * 256;
            int j = v >> 4, d4 = v & 15;
            float4 f = *(const float4*)&xb[(k0row + j) * ND + d4 * 4];
            uint4 u = { to_tf32(f.x), to_tf32(f.y), to_tf32(f.z), to_tf32(f.w) };
            *(uint4*)&Xs[j][d4 * 4] = u;
        }
        __syncthreads();

        #pragma unroll
        for (int ks = 0; ks < 8; ks++) {
            const int k0 = ks * 8;
            uint32_t a0 = As[qr][k0 + qc];
            uint32_t a1 = As[qr + 8][k0 + qc];
            uint32_t a2 = As[qr][k0 + qc + 4];
            uint32_t a3 = As[qr + 8][k0 + qc + 4];
            uint32_t b0 = Xs[k0 + qc][nt * 8 + qr];
            uint32_t b1 = Xs[k0 + qc + 4][nt * 8 + qr];
            mma_tf32(acc, a0, a1, a2, a3, b0, b1);
        }
    }

    // partial agg for rows 0..7
    float* ap = g_aggp + ((b * 4 + seg) * NN + i0 + qr) * ND + nt * 8 + qc * 2;
    ap[0] = acc[0];
    ap[1] = acc[1];
}

// ---------------------------------------------------------------------------
// Phase 2b: combine partials -> agg, h = agg@pw + x@pwo + biases,
// BN partial sums. grid (32, NB), 16 rows/block.
// ---------------------------------------------------------------------------
__global__ __launch_bounds__(256) void kH(
    const float* __restrict__ x,
    const float* __restrict__ pw,
    const float* __restrict__ pwb,
    const float* __restrict__ pwo,
    const float* __restrict__ pwob)
{
    __shared__ float agg_s[16][64];
    __shared__ float Xi[16][64];
    __shared__ float hs[16][64];
    __shared__ float inv_s[16];

    const int t = threadIdx.x;
    const int b = blockIdx.y;
    const int i0 = blockIdx.x * 16;
    const float* xb = x + b * NN * ND;

    if (t < 16) {
        float s = 0.f;
        #pragma unroll
        for (int seg = 0; seg < 4; seg++)
            s += g_sump[(b * 4 + seg) * NN + i0 + t];
        inv_s[t] = 1.f / s;
    }
    for (int idx = t; idx < 16 * 64; idx += 256)
        Xi[idx >> 6][idx & 63] = xb[(i0 + (idx >> 6)) * ND + (idx & 63)];
    __syncthreads();

    for (int idx = t; idx < 16 * 64; idx += 256) {
        int r = idx >> 6, d = idx & 63;
        float s = 0.f;
        #pragma unroll
        for (int seg = 0; seg < 4; seg++)
            s += g_aggp[((b * 4 + seg) * NN + i0 + r) * ND + d];
        agg_s[r][d] = s * inv_s[r];
    }
    __syncthreads();

    {
        int e = t & 63, rg = t >> 6;
        float h0 = pwb[e] + pwob[e];
        float hv[4] = { h0, h0, h0, h0 };
        #pragma unroll 8
        for (int d = 0; d < 64; d++) {
            float pwv = pw[d * 64 + e];
            float pov = pwo[d * 64 + e];
            #pragma unroll
            for (int k = 0; k < 4; k++) {
                int rr = rg * 4 + k;
                hv[k] += agg_s[rr][d] * pwv + Xi[rr][d] * pov;
            }
        }
        #pragma unroll
        for (int k = 0; k < 4; k++) {
            int rr = rg * 4 + k;
            g_h[(b * NN + i0 + rr) * ND + e] = hv[k];
            hs[rr][e] = hv[k];
        }
    }
    __syncthreads();

    if (t < 128) {
        int f = t & 63;
        float s = 0.f;
        if (t < 64) {
            #pragma unroll
            for (int w = 0; w < 16; w++) s += hs[w][f];
        } else {
            #pragma unroll
            for (int w = 0; w < 16; w++) { float v = hs[w][f]; s += v * v; }
        }
        g_part[(b * 32 + blockIdx.x) * 128 + t] = s;
    }
}

// ---------------------------------------------------------------------------
// kTail: stats reduce (64 partial blocks) -> BN+SELU+pool -> stable rank ->
// scatter. One block per batch.
// ---------------------------------------------------------------------------
__global__ __launch_bounds__(512) void kTail(
    const float* __restrict__ bn_g, const float* __restrict__ bn_b,
    const float* __restrict__ pool_w, const float* __restrict__ pool_b,
    float* __restrict__ out)
{
    __shared__ float red1[512], red2[512];
    __shared__ float a_s[64], c_s[64], pw_s[64];
    __shared__ float wv_s[512];

    const int t = threadIdx.x;
    const int b = blockIdx.x;

    {
        int f = t & 63, grp = t >> 6;
        float s = 0.f, q = 0.f;
        #pragma unroll
        for (int blk = grp; blk < 64; blk += 8) {
            s += g_part[blk * 128 + f];
            q += g_part[blk * 128 + 64 + f];
        }
        red1[t] = s;
        red2[t] = q;
        __syncthreads();
        if (t < 64) {
            float S = 0.f, Q = 0.f;
            #pragma unroll
            for (int g = 0; g < 8; g++) { S += red1[g * 64 + t]; Q += red2[g * 64 + t]; }
            float mean = S * (1.f / (NB * NN));
            float var = fmaxf(Q * (1.f / (NB * NN)) - mean * mean, 0.f);
            float a = rsqrtf(var + BN_EPS) * bn_g[t];
            a_s[t] = a;
            c_s[t] = bn_b[t] - mean * a;
            pw_s[t] = pool_w[t];
        }
        __syncthreads();
    }

    const float* hr = g_h + (b * NN + t) * ND;
    float4 hv[16];
    #pragma unroll
    for (int q = 0; q < 16; q++) hv[q] = *(const float4*)&hr[q * 4];

    float p = 0.f;
    #pragma unroll
    for (int q = 0; q < 16; q++) {
        #pragma unroll
        for (int c = 0; c < 4; c++) {
            int e = q * 4 + c;
            float v = (c == 0 ? hv[q].x : c == 1 ? hv[q].y : c == 2 ? hv[q].z : hv[q].w);
            float hn = v * a_s[e] + c_s[e];
            float s = hn > 0.f ? SELU_SCALE * hn
                               : SELU_SCALE * SELU_ALPHA * (__expf(hn) - 1.f);
            p += s * pw_s[e];
            if (c == 0) hv[q].x = s; else if (c == 1) hv[q].y = s;
            else if (c == 2) hv[q].z = s; else hv[q].w = s;
        }
    }
    float w = 1.f / (1.f + __expf(-(p + pool_b[0])));
    wv_s[t] = w;
    __syncthreads();

    int rank = 0;
    #pragma unroll 8
    for (int j = 0; j < NN; j++) {
        float u = wv_s[j];
        rank += (u > w) || (u == w && j < t);
    }

    if (rank < KN) {
        float* dp = out + (b * KN + rank) * ND;
        #pragma unroll
        for (int q = 0; q < 16; q++) {
            float4 o = hv[q];
            o.x *= w; o.y *= w; o.z *= w; o.w *= w;
            *(float4*)&dp[q * 4] = o;
        }
    }
}

// ---------------------------------------------------------------------------
// Launch (graph-capturable): 4 kernels.
// ---------------------------------------------------------------------------
extern "C" void kernel_launch(void* const* d_in, const int* in_sizes, int n_in,
                              void* d_out, int out_size)
{
    const float* x     = (const float*)d_in[0];
    const float* apw   = (const float*)d_in[1];
    const float* apb   = (const float*)d_in[2];
    const float* awt   = (const float*)d_in[3];
    const float* pw    = (const float*)d_in[4];
    const float* pwb   = (const float*)d_in[5];
    const float* pwo   = (const float*)d_in[6];
    const float* pwob  = (const float*)d_in[7];
    const float* bn_g  = (const float*)d_in[8];
    const float* bn_b  = (const float*)d_in[9];
    const float* poolw = (const float*)d_in[10];
    const float* poolb = (const float*)d_in[11];
    float* out = (float*)d_out;

    kScores<<<dim3(NN / 2, NB), 256>>>(x, apw, apb, awt);
    kAggP<<<dim3(NN / 8, 4, NB), 256>>>(x);
    kH<<<dim3(NN / 16, NB), 256>>>(x, pw, pwb, pwo, pwob);
    kTail<<<NB, 512>>>(bn_g, bn_b, poolw, poolb, out);
}

// round 14
// speedup vs baseline: 1.1993x; 1.1993x over previous
#include <cuda_runtime.h>
#include <cuda_bf16.h>
#include <cstdint>

// ---------------------------------------------------------------------------
// B=2, N=512, D_IN=D_OUT=64, TEMP=100, POOL_K=0.5 -> kn=256
// ---------------------------------------------------------------------------
#define NB 2
#define NN 512
#define ND 64
#define KN 256
#define TEMP_INV (1.0f/100.0f)
#define BN_EPS 1e-5f
#define SELU_SCALE 1.0507009873554804934193349852946f
#define SELU_ALPHA 1.6732632423543772848170429916717f

__device__ float g_scores[NB*NN*NN];
__device__ float g_h[NB*NN*ND];
__device__ float g_part[128*128];   // per-kAgg-block partial BN stats

__device__ __forceinline__ float tanh_approx(float x) {
    float r;
    asm("tanh.approx.f32 %0, %1;" : "=f"(r) : "f"(x));
    return r;
}
__device__ __forceinline__ uint32_t to_tf32(float f) {
    uint32_t u;
    asm("cvt.rna.tf32.f32 %0, %1;" : "=r"(u) : "f"(f));
    return u;
}
__device__ __forceinline__ void mma_tf32(float c[4], uint32_t a0, uint32_t a1,
                                         uint32_t a2, uint32_t a3,
                                         uint32_t b0, uint32_t b1) {
    asm("mma.sync.aligned.m16n8k8.row.col.f32.tf32.tf32.f32 "
        "{%0,%1,%2,%3}, {%4,%5,%6,%7}, {%8,%9}, {%0,%1,%2,%3};"
        : "+f"(c[0]), "+f"(c[1]), "+f"(c[2]), "+f"(c[3])
        : "r"(a0), "r"(a1), "r"(a2), "r"(a3), "r"(b0), "r"(b1));
}
__device__ __forceinline__ void mma_bf16(float c[4], const uint32_t a[4],
                                         uint32_t b0, uint32_t b1) {
    asm("mma.sync.aligned.m16n8k16.row.col.f32.bf16.bf16.f32 "
        "{%0,%1,%2,%3}, {%4,%5,%6,%7}, {%8,%9}, {%0,%1,%2,%3};"
        : "+f"(c[0]), "+f"(c[1]), "+f"(c[2]), "+f"(c[3])
        : "r"(a[0]), "r"(a[1]), "r"(a[2]), "r"(a[3]), "r"(b0), "r"(b1));
}
__device__ __forceinline__ void ldsm_x4(uint32_t r[4], uint32_t addr) {
    asm volatile("ldmatrix.sync.aligned.m8n8.x4.shared.b16 {%0,%1,%2,%3}, [%4];"
        : "=r"(r[0]), "=r"(r[1]), "=r"(r[2]), "=r"(r[3]) : "r"(addr));
}

// ---------------------------------------------------------------------------
// Phase 1 (bf16 tensor cores + ldmatrix, round-12 exact): scores upper
// triangle via symmetry.
// ---------------------------------------------------------------------------
__global__ __launch_bounds__(256) void kScores(
    const float* __restrict__ x,
    const float* __restrict__ apw,
    const float* __restrict__ apb,
    const float* __restrict__ awt)
{
    __shared__ __align__(16) __nv_bfloat16 Xs[64][72];  // [j][d]
    __shared__ __align__(16) __nv_bfloat16 Wt[64][72];  // [e][d]
    __shared__ float spart[2][64];
    __shared__ float xi_s[64], ab_s[64], aw_s[64];

    const int t = threadIdx.x;
    const int p = blockIdx.x;
    const int b = blockIdx.y;
    const float* xb = x + b * NN * ND;

    const int warp = t >> 5, lane = t & 31;
    const int jt = (warp & 3) * 16;
    const int eh = (warp >> 2) * 32;
    const int qr = lane >> 2, qc = lane & 3;

    if (t < 64) { ab_s[t] = apb[t]; aw_s[t] = awt[t]; }

    const uint32_t xsBase = (uint32_t)__cvta_generic_to_shared(&Xs[0][0]);
    const uint32_t wtBase = (uint32_t)__cvta_generic_to_shared(&Wt[0][0]);
    const uint32_t aAddr = xsBase + (jt + (lane & 15)) * 144 + (lane >> 4) * 16;
    const uint32_t bAddr1 = wtBase +
        (eh + (lane >> 4) * 8 + (lane & 7)) * 144 + ((lane >> 3) & 1) * 16;
    const uint32_t bAddr2 = bAddr1 + 16 * 144;

    #pragma unroll 1
    for (int r = 0; r < 2; r++) {
        const int i = r ? (NN - 1 - p) : p;
        __syncthreads();
        if (t < 64) xi_s[t] = xb[i * ND + t];
        __syncthreads();

        #pragma unroll
        for (int k = 0; k < 16; k++) {
            int idx = t + k * 256;
            int d = idx >> 6, e = idx & 63;
            Wt[e][d] = __float2bfloat16(xi_s[d] * apw[idx]);
        }

        for (int jc = i >> 6; jc < 8; jc++) {
            #pragma unroll
            for (int k = 0; k < 4; k++) {
                int v = t + k * 256;
                int j = v >> 4, d4 = v & 15;
                float4 f = *(const float4*)&xb[(jc * 64 + j) * ND + d4 * 4];
                __nv_bfloat162 lo = __float22bfloat162_rn(make_float2(f.x, f.y));
                __nv_bfloat162 hi = __float22bfloat162_rn(make_float2(f.z, f.w));
                uint2 u = { *(uint32_t*)&lo, *(uint32_t*)&hi };
                *(uint2*)&Xs[j][d4 * 4] = u;
            }
            __syncthreads();

            float acc[4][4] = {};
            #pragma unroll
            for (int ks = 0; ks < 4; ks++) {
                uint32_t a[4], b01[4], b23[4];
                ldsm_x4(a,   aAddr  + ks * 32);
                ldsm_x4(b01, bAddr1 + ks * 32);
                ldsm_x4(b23, bAddr2 + ks * 32);
                mma_bf16(acc[0], a, b01[0], b01[1]);
                mma_bf16(acc[1], a, b01[2], b01[3]);
                mma_bf16(acc[2], a, b23[0], b23[1]);
                mma_bf16(acc[3], a, b23[2], b23[3]);
            }

            float s0 = 0.f, s1 = 0.f;
            #pragma unroll
            for (int et = 0; et < 4; et++) {
                int e = eh + et * 8 + 2 * qc;
                s0 += aw_s[e]     * tanh_approx(acc[et][0] + ab_s[e]);
                s0 += aw_s[e + 1] * tanh_approx(acc[et][1] + ab_s[e + 1]);
                s1 += aw_s[e]     * tanh_approx(acc[et][2] + ab_s[e]);
                s1 += aw_s[e + 1] * tanh_approx(acc[et][3] + ab_s[e + 1]);
            }
            s0 += __shfl_xor_sync(0xffffffffu, s0, 1);
            s0 += __shfl_xor_sync(0xffffffffu, s0, 2);
            s1 += __shfl_xor_sync(0xffffffffu, s1, 1);
            s1 += __shfl_xor_sync(0xffffffffu, s1, 2);
            if (qc == 0) {
                spart[warp >> 2][jt + qr] = s0;
                spart[warp >> 2][jt + qr + 8] = s1;
            }
            __syncthreads();

            if (t < 64) {
                int j = jc * 64 + t;
                if (j >= i) {
                    float s = spart[0][t] + spart[1][t];
                    g_scores[(b * NN + i) * NN + j] = s;
                    g_scores[(b * NN + j) * NN + i] = s;
                }
            }
            __syncthreads();
        }
    }
}

// ---------------------------------------------------------------------------
// Phase 2 (round-12 exact kAgg v2): 8 rows/block, grid (64, NB).
// No-max softmax in registers; tf32 MMA with zero-padded A rows 8..15.
// ---------------------------------------------------------------------------
__global__ __launch_bounds__(256) void kAgg(
    const float* __restrict__ x,
    const float* __restrict__ pw,
    const float* __restrict__ pwb,
    const float* __restrict__ pwo,
    const float* __restrict__ pwob)
{
    __shared__ uint32_t As[16][68];
    __shared__ __align__(16) uint32_t Xs[64][72];
    __shared__ float agg_s[8][64];
    __shared__ float Xi[8][64];
    __shared__ float hs[8][64];

    const int t = threadIdx.x;
    const int warp = t >> 5, lane = t & 31;
    const int qr = lane >> 2, qc = lane & 3;
    const int nt = warp;
    const int b = blockIdx.y;
    const int i0 = blockIdx.x * 8;
    const float* xb = x + b * NN * ND;

    for (int idx = t; idx < 8 * 64; idx += 256)
        As[8 + (idx >> 6)][idx & 63] = 0;
    for (int idx = t; idx < 8 * 64; idx += 256)
        Xi[idx >> 6][idx & 63] = xb[(i0 + (idx >> 6)) * ND + (idx & 63)];

    float sv[16];
    {
        const float* srow = g_scores + (b * NN + i0 + warp) * NN;
        float sum = 0.f;
        #pragma unroll
        for (int q = 0; q < 16; q++) {
            sv[q] = __expf(srow[q * 32 + lane] * TEMP_INV);
            sum += sv[q];
        }
        #pragma unroll
        for (int o = 16; o > 0; o >>= 1)
            sum += __shfl_xor_sync(0xffffffffu, sum, o);
        float inv = 1.f / sum;
        #pragma unroll
        for (int q = 0; q < 16; q++) sv[q] *= inv;
    }

    float acc[4] = {};
    #pragma unroll
    for (int jc = 0; jc < 8; jc++) {
        __syncthreads();
        As[warp][lane]      = to_tf32(sv[2 * jc]);
        As[warp][32 + lane] = to_tf32(sv[2 * jc + 1]);
        #pragma unroll
        for (int k = 0; k < 4; k++) {
            int v = t + k * 256;
            int j = v >> 4, d4 = v & 15;
            float4 f = *(const float4*)&xb[(jc * 64 + j) * ND + d4 * 4];
            uint4 u = { to_tf32(f.x), to_tf32(f.y), to_tf32(f.z), to_tf32(f.w) };
            *(uint4*)&Xs[j][d4 * 4] = u;
        }
        __syncthreads();

        #pragma unroll
        for (int ks = 0; ks < 8; ks++) {
            const int k0 = ks * 8;
            uint32_t a0 = As[qr][k0 + qc];
            uint32_t a1 = As[qr + 8][k0 + qc];
            uint32_t a2 = As[qr][k0 + qc + 4];
            uint32_t a3 = As[qr + 8][k0 + qc + 4];
            uint32_t b0 = Xs[k0 + qc][nt * 8 + qr];
            uint32_t b1 = Xs[k0 + qc + 4][nt * 8 + qr];
            mma_tf32(acc, a0, a1, a2, a3, b0, b1);
        }
    }

    agg_s[qr][nt * 8 + qc * 2]     = acc[0];
    agg_s[qr][nt * 8 + qc * 2 + 1] = acc[1];
    __syncthreads();

    {
        int e = t & 63, rg = t >> 6;
        float h0 = pwb[e] + pwob[e];
        float hv[2] = { h0, h0 };
        #pragma unroll 8
        for (int d = 0; d < 64; d++) {
            float pwv = pw[d * 64 + e];
            float pov = pwo[d * 64 + e];
            #pragma unroll
            for (int k = 0; k < 2; k++) {
                int rr = rg * 2 + k;
                hv[k] += agg_s[rr][d] * pwv + Xi[rr][d] * pov;
            }
        }
        #pragma unroll
        for (int k = 0; k < 2; k++) {
            int rr = rg * 2 + k;
            g_h[(b * NN + i0 + rr) * ND + e] = hv[k];
            hs[rr][e] = hv[k];
        }
    }
    __syncthreads();

    if (t < 128) {
        int f = t & 63;
        float s = 0.f;
        if (t < 64) {
            #pragma unroll
            for (int w = 0; w < 8; w++) s += hs[w][f];
        } else {
            #pragma unroll
            for (int w = 0; w < 8; w++) { float v = hs[w][f]; s += v * v; }
        }
        g_part[(b * 64 + blockIdx.x) * 128 + t] = s;
    }
}

// ---------------------------------------------------------------------------
// kTail v2 (PARALLEL): grid (8, NB), 256 threads, 64 output rows per block.
// Each block: redundant deterministic stats reduce; redundant gate pass over
// all 512 rows (thread -> rows t, t+256; own-block rows' selu vals kept in
// smem); rank own 64 rows with 4 threads/row (128 comps each); scatter with
// 4 threads/row.
// ---------------------------------------------------------------------------
__global__ __launch_bounds__(256) void kTail(
    const float* __restrict__ bn_g, const float* __restrict__ bn_b,
    const float* __restrict__ pool_w, const float* __restrict__ pool_b,
    float* __restrict__ out)
{
    __shared__ float red1[256], red2[256];
    __shared__ float a_s[64], c_s[64], pw_s[64];
    __shared__ float wv_s[512];
    __shared__ __align__(16) float hsel[64][68];
    __shared__ float rank_p[64][4];
    __shared__ int rank_s[64];

    const int t = threadIdx.x;
    const int b = blockIdx.y;
    const int i0 = blockIdx.x * 64;

    // ---- stats reduce (redundant per block, deterministic)
    {
        int f = t & 63, grp = t >> 6;
        float s = 0.f, q = 0.f;
        #pragma unroll 8
        for (int blk = grp; blk < 128; blk += 4) {
            s += g_part[blk * 128 + f];
            q += g_part[blk * 128 + 64 + f];
        }
        red1[t] = s;
        red2[t] = q;
        __syncthreads();
        if (t < 64) {
            float S = red1[t] + red1[64 + t] + red1[128 + t] + red1[192 + t];
            float Q = red2[t] + red2[64 + t] + red2[128 + t] + red2[192 + t];
            float mean = S * (1.f / (NB * NN));
            float var = fmaxf(Q * (1.f / (NB * NN)) - mean * mean, 0.f);
            float a = rsqrtf(var + BN_EPS) * bn_g[t];
            a_s[t] = a;
            c_s[t] = bn_b[t] - mean * a;
            pw_s[t] = pool_w[t];
        }
        __syncthreads();
    }

    const float pb = pool_b[0];

    // ---- gate pass: thread handles rows t and t+256 (full batch, redundant)
    #pragma unroll
    for (int half = 0; half < 2; half++) {
        int r = t + half * 256;
        const float* hr = g_h + (b * NN + r) * ND;
        bool own = (unsigned)(r - i0) < 64u;
        float p = 0.f;
        #pragma unroll
        for (int q = 0; q < 16; q++) {
            float4 v = *(const float4*)&hr[q * 4];
            float4 o;
            {
                int e = q * 4;
                float hn = v.x * a_s[e] + c_s[e];
                o.x = hn > 0.f ? SELU_SCALE * hn
                               : SELU_SCALE * SELU_ALPHA * (__expf(hn) - 1.f);
                p += o.x * pw_s[e];
                hn = v.y * a_s[e + 1] + c_s[e + 1];
                o.y = hn > 0.f ? SELU_SCALE * hn
                               : SELU_SCALE * SELU_ALPHA * (__expf(hn) - 1.f);
                p += o.y * pw_s[e + 1];
                hn = v.z * a_s[e + 2] + c_s[e + 2];
                o.z = hn > 0.f ? SELU_SCALE * hn
                               : SELU_SCALE * SELU_ALPHA * (__expf(hn) - 1.f);
                p += o.z * pw_s[e + 2];
                hn = v.w * a_s[e + 3] + c_s[e + 3];
                o.w = hn > 0.f ? SELU_SCALE * hn
                               : SELU_SCALE * SELU_ALPHA * (__expf(hn) - 1.f);
                p += o.w * pw_s[e + 3];
            }
            if (own) *(float4*)&hsel[r - i0][q * 4] = o;
        }
        wv_s[r] = 1.f / (1.f + __expf(-(p + pb)));
    }
    __syncthreads();

    // ---- rank own 64 rows: 4 threads/row x 128 comparisons
    {
        int lr = t & 63, seg = t >> 6;
        int row = i0 + lr;
        float w = wv_s[row];
        int pr = 0;
        #pragma unroll 8
        for (int j = seg * 128; j < seg * 128 + 128; j++) {
            float u = wv_s[j];
            pr += (u > w) || (u == w && j < row);
        }
        rank_p[lr][seg] = (float)pr;
    }
    __syncthreads();
    if (t < 64)
        rank_s[t] = (int)(rank_p[t][0] + rank_p[t][1] + rank_p[t][2] + rank_p[t][3]);
    __syncthreads();

    // ---- scatter: 4 threads/row, 16 floats each
    {
        int lr = t >> 2, part = t & 3;
        int rk = rank_s[lr];
        if (rk < KN) {
            float w = wv_s[i0 + lr];
            float* dp = out + (b * KN + rk) * ND + part * 16;
            #pragma unroll
            for (int q = 0; q < 4; q++) {
                float4 o = *(float4*)&hsel[lr][part * 16 + q * 4];
                o.x *= w; o.y *= w; o.z *= w; o.w *= w;
                *(float4*)&dp[q * 4] = o;
            }
        }
    }
}

// ---------------------------------------------------------------------------
// Launch (graph-capturable): 3 kernels.
// ---------------------------------------------------------------------------
extern "C" void kernel_launch(void* const* d_in, const int* in_sizes, int n_in,
                              void* d_out, int out_size)
{
    const float* x     = (const float*)d_in[0];
    const float* apw   = (const float*)d_in[1];
    const float* apb   = (const float*)d_in[2];
    const float* awt   = (const float*)d_in[3];
    const float* pw    = (const float*)d_in[4];
    const float* pwb   = (const float*)d_in[5];
    const float* pwo   = (const float*)d_in[6];
    const float* pwob  = (const float*)d_in[7];
    const float* bn_g  = (const float*)d_in[8];
    const float* bn_b  = (const float*)d_in[9];
    const float* poolw = (const float*)d_in[10];
    const float* poolb = (const float*)d_in[11];
    float* out = (float*)d_out;

    kScores<<<dim3(NN / 2, NB), 256>>>(x, apw, apb, awt);
    kAgg<<<dim3(NN / 8, NB), 256>>>(x, pw, pwb, pwo, pwob);
    kTail<<<dim3(8, NB), 256>>>(bn_g, bn_b, poolw, poolb, out);
}

// round 15
// speedup vs baseline: 1.2208x; 1.0179x over previous
#include <cuda_runtime.h>
#include <cuda_bf16.h>
#include <cstdint>

// ---------------------------------------------------------------------------
// B=2, N=512, D_IN=D_OUT=64, TEMP=100, POOL_K=0.5 -> kn=256
// ---------------------------------------------------------------------------
#define NB 2
#define NN 512
#define ND 64
#define KN 256
#define TEMP_INV (1.0f/100.0f)
#define BN_EPS 1e-5f
#define SELU_SCALE 1.0507009873554804934193349852946f
#define SELU_ALPHA 1.6732632423543772848170429916717f

__device__ float g_scores[NB*NN*NN];
__device__ float g_h[NB*NN*ND];
__device__ float g_part[128*128];   // per-kAgg-block partial BN stats

__device__ __forceinline__ float tanh_approx(float x) {
    float r;
    asm("tanh.approx.f32 %0, %1;" : "=f"(r) : "f"(x));
    return r;
}
__device__ __forceinline__ uint32_t to_tf32(float f) {
    uint32_t u;
    asm("cvt.rna.tf32.f32 %0, %1;" : "=r"(u) : "f"(f));
    return u;
}
__device__ __forceinline__ void mma_tf32(float c[4], uint32_t a0, uint32_t a1,
                                         uint32_t a2, uint32_t a3,
                                         uint32_t b0, uint32_t b1) {
    asm("mma.sync.aligned.m16n8k8.row.col.f32.tf32.tf32.f32 "
        "{%0,%1,%2,%3}, {%4,%5,%6,%7}, {%8,%9}, {%0,%1,%2,%3};"
        : "+f"(c[0]), "+f"(c[1]), "+f"(c[2]), "+f"(c[3])
        : "r"(a0), "r"(a1), "r"(a2), "r"(a3), "r"(b0), "r"(b1));
}
__device__ __forceinline__ void mma_bf16(float c[4], const uint32_t a[4],
                                         uint32_t b0, uint32_t b1) {
    asm("mma.sync.aligned.m16n8k16.row.col.f32.bf16.bf16.f32 "
        "{%0,%1,%2,%3}, {%4,%5,%6,%7}, {%8,%9}, {%0,%1,%2,%3};"
        : "+f"(c[0]), "+f"(c[1]), "+f"(c[2]), "+f"(c[3])
        : "r"(a[0]), "r"(a[1]), "r"(a[2]), "r"(a[3]), "r"(b0), "r"(b1));
}
__device__ __forceinline__ void ldsm_x4(uint32_t r[4], uint32_t addr) {
    asm volatile("ldmatrix.sync.aligned.m8n8.x4.shared.b16 {%0,%1,%2,%3}, [%4];"
        : "=r"(r[0]), "=r"(r[1]), "=r"(r[2]), "=r"(r[3]) : "r"(addr));
}

// ---------------------------------------------------------------------------
// Phase 1 (bf16 tensor cores + ldmatrix + HOISTED B-fragments):
// scores upper triangle via symmetry. B (Wt) fragments are constant across
// all chunks of a row -> loaded once into 32 regs; per-chunk LDSM 12 -> 4.
// ---------------------------------------------------------------------------
__global__ __launch_bounds__(256) void kScores(
    const float* __restrict__ x,
    const float* __restrict__ apw,
    const float* __restrict__ apb,
    const float* __restrict__ awt)
{
    __shared__ __align__(16) __nv_bfloat16 Xs[64][72];  // [j][d]
    __shared__ __align__(16) __nv_bfloat16 Wt[64][72];  // [e][d]
    __shared__ float spart[2][64];
    __shared__ float xi_s[64], ab_s[64], aw_s[64];

    const int t = threadIdx.x;
    const int p = blockIdx.x;
    const int b = blockIdx.y;
    const float* xb = x + b * NN * ND;

    const int warp = t >> 5, lane = t & 31;
    const int jt = (warp & 3) * 16;
    const int eh = (warp >> 2) * 32;
    const int qr = lane >> 2, qc = lane & 3;

    if (t < 64) { ab_s[t] = apb[t]; aw_s[t] = awt[t]; }

    const uint32_t xsBase = (uint32_t)__cvta_generic_to_shared(&Xs[0][0]);
    const uint32_t wtBase = (uint32_t)__cvta_generic_to_shared(&Wt[0][0]);
    const uint32_t aAddr = xsBase + (jt + (lane & 15)) * 144 + (lane >> 4) * 16;
    const uint32_t bAddr1 = wtBase +
        (eh + (lane >> 4) * 8 + (lane & 7)) * 144 + ((lane >> 3) & 1) * 16;
    const uint32_t bAddr2 = bAddr1 + 16 * 144;

    #pragma unroll 1
    for (int r = 0; r < 2; r++) {
        const int i = r ? (NN - 1 - p) : p;
        __syncthreads();
        if (t < 64) xi_s[t] = xb[i * ND + t];
        __syncthreads();

        #pragma unroll
        for (int k = 0; k < 16; k++) {
            int idx = t + k * 256;
            int d = idx >> 6, e = idx & 63;
            Wt[e][d] = __float2bfloat16(xi_s[d] * apw[idx]);
        }
        __syncthreads();

        // hoisted B fragments (constant for this row)
        uint32_t bf1[4][4], bf2[4][4];
        #pragma unroll
        for (int ks = 0; ks < 4; ks++) {
            ldsm_x4(bf1[ks], bAddr1 + ks * 32);
            ldsm_x4(bf2[ks], bAddr2 + ks * 32);
        }

        for (int jc = i >> 6; jc < 8; jc++) {
            #pragma unroll
            for (int k = 0; k < 4; k++) {
                int v = t + k * 256;
                int j = v >> 4, d4 = v & 15;
                float4 f = *(const float4*)&xb[(jc * 64 + j) * ND + d4 * 4];
                __nv_bfloat162 lo = __float22bfloat162_rn(make_float2(f.x, f.y));
                __nv_bfloat162 hi = __float22bfloat162_rn(make_float2(f.z, f.w));
                uint2 u = { *(uint32_t*)&lo, *(uint32_t*)&hi };
                *(uint2*)&Xs[j][d4 * 4] = u;
            }
            __syncthreads();

            float acc[4][4] = {};
            #pragma unroll
            for (int ks = 0; ks < 4; ks++) {
                uint32_t a[4];
                ldsm_x4(a, aAddr + ks * 32);
                mma_bf16(acc[0], a, bf1[ks][0], bf1[ks][1]);
                mma_bf16(acc[1], a, bf1[ks][2], bf1[ks][3]);
                mma_bf16(acc[2], a, bf2[ks][0], bf2[ks][1]);
                mma_bf16(acc[3], a, bf2[ks][2], bf2[ks][3]);
            }

            float s0 = 0.f, s1 = 0.f;
            #pragma unroll
            for (int et = 0; et < 4; et++) {
                int e = eh + et * 8 + 2 * qc;
                s0 += aw_s[e]     * tanh_approx(acc[et][0] + ab_s[e]);
                s0 += aw_s[e + 1] * tanh_approx(acc[et][1] + ab_s[e + 1]);
                s1 += aw_s[e]     * tanh_approx(acc[et][2] + ab_s[e]);
                s1 += aw_s[e + 1] * tanh_approx(acc[et][3] + ab_s[e + 1]);
            }
            s0 += __shfl_xor_sync(0xffffffffu, s0, 1);
            s0 += __shfl_xor_sync(0xffffffffu, s0, 2);
            s1 += __shfl_xor_sync(0xffffffffu, s1, 1);
            s1 += __shfl_xor_sync(0xffffffffu, s1, 2);
            if (qc == 0) {
                spart[warp >> 2][jt + qr] = s0;
                spart[warp >> 2][jt + qr + 8] = s1;
            }
            __syncthreads();

            if (t < 64) {
                int j = jc * 64 + t;
                if (j >= i) {
                    float s = spart[0][t] + spart[1][t];
                    g_scores[(b * NN + i) * NN + j] = s;
                    g_scores[(b * NN + j) * NN + i] = s;
                }
            }
            __syncthreads();
        }
    }
}

// ---------------------------------------------------------------------------
// Phase 2 (round-14 exact kAgg v2): 8 rows/block, grid (64, NB).
// No-max softmax in registers; tf32 MMA with zero-padded A rows 8..15.
// ---------------------------------------------------------------------------
__global__ __launch_bounds__(256) void kAgg(
    const float* __restrict__ x,
    const float* __restrict__ pw,
    const float* __restrict__ pwb,
    const float* __restrict__ pwo,
    const float* __restrict__ pwob)
{
    __shared__ uint32_t As[16][68];
    __shared__ __align__(16) uint32_t Xs[64][72];
    __shared__ float agg_s[8][64];
    __shared__ float Xi[8][64];
    __shared__ float hs[8][64];

    const int t = threadIdx.x;
    const int warp = t >> 5, lane = t & 31;
    const int qr = lane >> 2, qc = lane & 3;
    const int nt = warp;
    const int b = blockIdx.y;
    const int i0 = blockIdx.x * 8;
    const float* xb = x + b * NN * ND;

    for (int idx = t; idx < 8 * 64; idx += 256)
        As[8 + (idx >> 6)][idx & 63] = 0;
    for (int idx = t; idx < 8 * 64; idx += 256)
        Xi[idx >> 6][idx & 63] = xb[(i0 + (idx >> 6)) * ND + (idx & 63)];

    float sv[16];
    {
        const float* srow = g_scores + (b * NN + i0 + warp) * NN;
        float sum = 0.f;
        #pragma unroll
        for (int q = 0; q < 16; q++) {
            sv[q] = __expf(srow[q * 32 + lane] * TEMP_INV);
            sum += sv[q];
        }
        #pragma unroll
        for (int o = 16; o > 0; o >>= 1)
            sum += __shfl_xor_sync(0xffffffffu, sum, o);
        float inv = 1.f / sum;
        #pragma unroll
        for (int q = 0; q < 16; q++) sv[q] *= inv;
    }

    float acc[4] = {};
    #pragma unroll
    for (int jc = 0; jc < 8; jc++) {
        __syncthreads();
        As[warp][lane]      = to_tf32(sv[2 * jc]);
        As[warp][32 + lane] = to_tf32(sv[2 * jc + 1]);
        #pragma unroll
        for (int k = 0; k < 4; k++) {
            int v = t + k * 256;
            int j = v >> 4, d4 = v & 15;
            float4 f = *(const float4*)&xb[(jc * 64 + j) * ND + d4 * 4];
            uint4 u = { to_tf32(f.x), to_tf32(f.y), to_tf32(f.z), to_tf32(f.w) };
            *(uint4*)&Xs[j][d4 * 4] = u;
        }
        __syncthreads();

        #pragma unroll
        for (int ks = 0; ks < 8; ks++) {
            const int k0 = ks * 8;
            uint32_t a0 = As[qr][k0 + qc];
            uint32_t a1 = As[qr + 8][k0 + qc];
            uint32_t a2 = As[qr][k0 + qc + 4];
            uint32_t a3 = As[qr + 8][k0 + qc + 4];
            uint32_t b0 = Xs[k0 + qc][nt * 8 + qr];
            uint32_t b1 = Xs[k0 + qc + 4][nt * 8 + qr];
            mma_tf32(acc, a0, a1, a2, a3, b0, b1);
        }
    }

    agg_s[qr][nt * 8 + qc * 2]     = acc[0];
    agg_s[qr][nt * 8 + qc * 2 + 1] = acc[1];
    __syncthreads();

    {
        int e = t & 63, rg = t >> 6;
        float h0 = pwb[e] + pwob[e];
        float hv[2] = { h0, h0 };
        #pragma unroll 8
        for (int d = 0; d < 64; d++) {
            float pwv = pw[d * 64 + e];
            float pov = pwo[d * 64 + e];
            #pragma unroll
            for (int k = 0; k < 2; k++) {
                int rr = rg * 2 + k;
                hv[k] += agg_s[rr][d] * pwv + Xi[rr][d] * pov;
            }
        }
        #pragma unroll
        for (int k = 0; k < 2; k++) {
            int rr = rg * 2 + k;
            g_h[(b * NN + i0 + rr) * ND + e] = hv[k];
            hs[rr][e] = hv[k];
        }
    }
    __syncthreads();

    if (t < 128) {
        int f = t & 63;
        float s = 0.f;
        if (t < 64) {
            #pragma unroll
            for (int w = 0; w < 8; w++) s += hs[w][f];
        } else {
            #pragma unroll
            for (int w = 0; w < 8; w++) { float v = hs[w][f]; s += v * v; }
        }
        g_part[(b * 64 + blockIdx.x) * 128 + t] = s;
    }
}

// ---------------------------------------------------------------------------
// kTail v2 (round-14 exact): grid (8, NB), 256 threads, 64 rows per block.
// ---------------------------------------------------------------------------
__global__ __launch_bounds__(256) void kTail(
    const float* __restrict__ bn_g, const float* __restrict__ bn_b,
    const float* __restrict__ pool_w, const float* __restrict__ pool_b,
    float* __restrict__ out)
{
    __shared__ float red1[256], red2[256];
    __shared__ float a_s[64], c_s[64], pw_s[64];
    __shared__ float wv_s[512];
    __shared__ __align__(16) float hsel[64][68];
    __shared__ float rank_p[64][4];
    __shared__ int rank_s[64];

    const int t = threadIdx.x;
    const int b = blockIdx.y;
    const int i0 = blockIdx.x * 64;

    {
        int f = t & 63, grp = t >> 6;
        float s = 0.f, q = 0.f;
        #pragma unroll 8
        for (int blk = grp; blk < 128; blk += 4) {
            s += g_part[blk * 128 + f];
            q += g_part[blk * 128 + 64 + f];
        }
        red1[t] = s;
        red2[t] = q;
        __syncthreads();
        if (t < 64) {
            float S = red1[t] + red1[64 + t] + red1[128 + t] + red1[192 + t];
            float Q = red2[t] + red2[64 + t] + red2[128 + t] + red2[192 + t];
            float mean = S * (1.f / (NB * NN));
            float var = fmaxf(Q * (1.f / (NB * NN)) - mean * mean, 0.f);
            float a = rsqrtf(var + BN_EPS) * bn_g[t];
            a_s[t] = a;
            c_s[t] = bn_b[t] - mean * a;
            pw_s[t] = pool_w[t];
        }
        __syncthreads();
    }

    const float pb = pool_b[0];

    #pragma unroll
    for (int half = 0; half < 2; half++) {
        int r = t + half * 256;
        const float* hr = g_h + (b * NN + r) * ND;
        bool own = (unsigned)(r - i0) < 64u;
        float p = 0.f;
        #pragma unroll
        for (int q = 0; q < 16; q++) {
            float4 v = *(const float4*)&hr[q * 4];
            float4 o;
            {
                int e = q * 4;
                float hn = v.x * a_s[e] + c_s[e];
                o.x = hn > 0.f ? SELU_SCALE * hn
                               : SELU_SCALE * SELU_ALPHA * (__expf(hn) - 1.f);
                p += o.x * pw_s[e];
                hn = v.y * a_s[e + 1] + c_s[e + 1];
                o.y = hn > 0.f ? SELU_SCALE * hn
                               : SELU_SCALE * SELU_ALPHA * (__expf(hn) - 1.f);
                p += o.y * pw_s[e + 1];
                hn = v.z * a_s[e + 2] + c_s[e + 2];
                o.z = hn > 0.f ? SELU_SCALE * hn
                               : SELU_SCALE * SELU_ALPHA * (__expf(hn) - 1.f);
                p += o.z * pw_s[e + 2];
                hn = v.w * a_s[e + 3] + c_s[e + 3];
                o.w = hn > 0.f ? SELU_SCALE * hn
                               : SELU_SCALE * SELU_ALPHA * (__expf(hn) - 1.f);
                p += o.w * pw_s[e + 3];
            }
            if (own) *(float4*)&hsel[r - i0][q * 4] = o;
        }
        wv_s[r] = 1.f / (1.f + __expf(-(p + pb)));
    }
    __syncthreads();

    {
        int lr = t & 63, seg = t >> 6;
        int row = i0 + lr;
        float w = wv_s[row];
        int pr = 0;
        #pragma unroll 8
        for (int j = seg * 128; j < seg * 128 + 128; j++) {
            float u = wv_s[j];
            pr += (u > w) || (u == w && j < row);
        }
        rank_p[lr][seg] = (float)pr;
    }
    __syncthreads();
    if (t < 64)
        rank_s[t] = (int)(rank_p[t][0] + rank_p[t][1] + rank_p[t][2] + rank_p[t][3]);
    __syncthreads();

    {
        int lr = t >> 2, part = t & 3;
        int rk = rank_s[lr];
        if (rk < KN) {
            float w = wv_s[i0 + lr];
            float* dp = out + (b * KN + rk) * ND + part * 16;
            #pragma unroll
            for (int q = 0; q < 4; q++) {
                float4 o = *(float4*)&hsel[lr][part * 16 + q * 4];
                o.x *= w; o.y *= w; o.z *= w; o.w *= w;
                *(float4*)&dp[q * 4] = o;
            }
        }
    }
}

// ---------------------------------------------------------------------------
// Launch (graph-capturable): 3 kernels.
// ---------------------------------------------------------------------------
extern "C" void kernel_launch(void* const* d_in, const int* in_sizes, int n_in,
                              void* d_out, int out_size)
{
    const float* x     = (const float*)d_in[0];
    const float* apw   = (const float*)d_in[1];
    const float* apb   = (const float*)d_in[2];
    const float* awt   = (const float*)d_in[3];
    const float* pw    = (const float*)d_in[4];
    const float* pwb   = (const float*)d_in[5];
    const float* pwo   = (const float*)d_in[6];
    const float* pwob  = (const float*)d_in[7];
    const float* bn_g  = (const float*)d_in[8];
    const float* bn_b  = (const float*)d_in[9];
    const float* poolw = (const float*)d_in[10];
    const float* poolb = (const float*)d_in[11];
    float* out = (float*)d_out;

    kScores<<<dim3(NN / 2, NB), 256>>>(x, apw, apb, awt);
    kAgg<<<dim3(NN / 8, NB), 256>>>(x, pw, pwb, pwo, pwob);
    kTail<<<dim3(8, NB), 256>>>(bn_g, bn_b, poolw, poolb, out);
}

// round 16
// speedup vs baseline: 1.2222x; 1.0012x over previous
#include <cuda_runtime.h>
#include <cuda_bf16.h>
#include <cstdint>

// ---------------------------------------------------------------------------
// B=2, N=512, D_IN=D_OUT=64, TEMP=100, POOL_K=0.5 -> kn=256
// ---------------------------------------------------------------------------
#define NB 2
#define NN 512
#define ND 64
#define KN 256
#define TEMP_INV (1.0f/100.0f)
#define BN_EPS 1e-5f
#define SELU_SCALE 1.0507009873554804934193349852946f
#define SELU_ALPHA 1.6732632423543772848170429916717f

__device__ float g_scores[NB*NN*NN];
__device__ float g_h[NB*NN*ND];
__device__ float g_part[128*128];            // per-kAgg-block partial BN stats
__device__ __nv_bfloat16 g_xbf[NB*NN*ND];    // bf16 copy of x (kPrep)

__device__ __forceinline__ float tanh_approx(float x) {
    float r;
    asm("tanh.approx.f32 %0, %1;" : "=f"(r) : "f"(x));
    return r;
}
__device__ __forceinline__ uint32_t to_tf32(float f) {
    uint32_t u;
    asm("cvt.rna.tf32.f32 %0, %1;" : "=r"(u) : "f"(f));
    return u;
}
__device__ __forceinline__ void mma_tf32(float c[4], uint32_t a0, uint32_t a1,
                                         uint32_t a2, uint32_t a3,
                                         uint32_t b0, uint32_t b1) {
    asm("mma.sync.aligned.m16n8k8.row.col.f32.tf32.tf32.f32 "
        "{%0,%1,%2,%3}, {%4,%5,%6,%7}, {%8,%9}, {%0,%1,%2,%3};"
        : "+f"(c[0]), "+f"(c[1]), "+f"(c[2]), "+f"(c[3])
        : "r"(a0), "r"(a1), "r"(a2), "r"(a3), "r"(b0), "r"(b1));
}
__device__ __forceinline__ void mma_bf16(float c[4], const uint32_t a[4],
                                         uint32_t b0, uint32_t b1) {
    asm("mma.sync.aligned.m16n8k16.row.col.f32.bf16.bf16.f32 "
        "{%0,%1,%2,%3}, {%4,%5,%6,%7}, {%8,%9}, {%0,%1,%2,%3};"
        : "+f"(c[0]), "+f"(c[1]), "+f"(c[2]), "+f"(c[3])
        : "r"(a[0]), "r"(a[1]), "r"(a[2]), "r"(a[3]), "r"(b0), "r"(b1));
}
__device__ __forceinline__ void ldsm_x4(uint32_t r[4], uint32_t addr) {
    asm volatile("ldmatrix.sync.aligned.m8n8.x4.shared.b16 {%0,%1,%2,%3}, [%4];"
        : "=r"(r[0]), "=r"(r[1]), "=r"(r[2]), "=r"(r[3]) : "r"(addr));
}
__device__ __forceinline__ void cp_async16(uint32_t smem, const void* g) {
    asm volatile("cp.async.cg.shared.global [%0], [%1], 16;"
        :: "r"(smem), "l"(g));
}
__device__ __forceinline__ void cp_commit() {
    asm volatile("cp.async.commit_group;");
}
template <int N>
__device__ __forceinline__ void cp_wait() {
    asm volatile("cp.async.wait_group %0;" :: "n"(N));
}

// ---------------------------------------------------------------------------
// kPrep: x (f32) -> g_xbf (bf16), once. 16384 threads x 1 float4.
// ---------------------------------------------------------------------------
__global__ __launch_bounds__(256) void kPrep(const float* __restrict__ x) {
    int idx = blockIdx.x * 256 + threadIdx.x;    // 0..16383
    float4 f = ((const float4*)x)[idx];
    __nv_bfloat162 lo = __float22bfloat162_rn(make_float2(f.x, f.y));
    __nv_bfloat162 hi = __float22bfloat162_rn(make_float2(f.z, f.w));
    uint2 u = { *(uint32_t*)&lo, *(uint32_t*)&hi };
    *(uint2*)&g_xbf[idx * 4] = u;
}

// ---------------------------------------------------------------------------
// Phase 1 v3 (bf16 MMA + ldmatrix + cp.async double-buffered chunk fill):
// scores upper triangle via symmetry. Block (p,b) -> rows i=p, 511-p.
// Per chunk: 512 x 16B cp.async from g_xbf (issued one chunk ahead),
// then 12 LDSM + 16 MMA + tanh epilogue. Global-load latency hidden.
// ---------------------------------------------------------------------------
__global__ __launch_bounds__(256) void kScores(
    const float* __restrict__ x,
    const float* __restrict__ apw,
    const float* __restrict__ apb,
    const float* __restrict__ awt)
{
    __shared__ __align__(16) __nv_bfloat16 Xs[2][64][72];  // double buffer
    __shared__ __align__(16) __nv_bfloat16 Wt[64][72];     // [e][d]
    __shared__ float spart[2][64];
    __shared__ float xi_s[64], ab_s[64], aw_s[64];

    const int t = threadIdx.x;
    const int p = blockIdx.x;
    const int b = blockIdx.y;
    const float* xb = x + b * NN * ND;
    const __nv_bfloat16* xbfb = g_xbf + b * NN * ND;

    const int warp = t >> 5, lane = t & 31;
    const int jt = (warp & 3) * 16;
    const int eh = (warp >> 2) * 32;
    const int qr = lane >> 2, qc = lane & 3;

    if (t < 64) { ab_s[t] = apb[t]; aw_s[t] = awt[t]; }

    const uint32_t xsBase = (uint32_t)__cvta_generic_to_shared(&Xs[0][0][0]);
    const uint32_t wtBase = (uint32_t)__cvta_generic_to_shared(&Wt[0][0]);
    const uint32_t aAddr0 = xsBase + (jt + (lane & 15)) * 144 + (lane >> 4) * 16;
    const uint32_t bAddr1 = wtBase +
        (eh + (lane >> 4) * 8 + (lane & 7)) * 144 + ((lane >> 3) & 1) * 16;
    const uint32_t bAddr2 = bAddr1 + 16 * 144;

    // per-thread cp.async segment coords (2 segments/thread/chunk)
    const int j0_ = t >> 3, s0_ = t & 7;              // seg t
    const int j1_ = (t + 256) >> 3, s1_ = t & 7;      // seg t+256 (s same: (t+256)&7==t&7)
    const uint32_t d0 = j0_ * 144 + s0_ * 16;
    const uint32_t d1 = j1_ * 144 + s1_ * 16;

    #pragma unroll 1
    for (int r = 0; r < 2; r++) {
        const int i = r ? (NN - 1 - p) : p;
        __syncthreads();
        if (t < 64) xi_s[t] = xb[i * ND + t];
        __syncthreads();

        // Wt[e][d] = bf16(x_i[d] * W[d][e])
        #pragma unroll
        for (int k = 0; k < 16; k++) {
            int idx = t + k * 256;
            int d = idx >> 6, e = idx & 63;
            Wt[e][d] = __float2bfloat16(xi_s[d] * apw[idx]);
        }

        const int jc0 = i >> 6;
        // prologue: async-fill first chunk into buf 0
        {
            const __nv_bfloat16* gsrc = xbfb + jc0 * 64 * ND;
            cp_async16(xsBase + d0, gsrc + j0_ * ND + s0_ * 8);
            cp_async16(xsBase + d1, gsrc + j1_ * ND + s1_ * 8);
            cp_commit();
        }

        for (int jc = jc0; jc < 8; jc++) {
            const int buf = (jc - jc0) & 1;
            const uint32_t bufOff = (uint32_t)buf * 9216;
            if (jc < 7) {   // prefetch next chunk into other buffer
                const __nv_bfloat16* gsrc = xbfb + (jc + 1) * 64 * ND;
                const uint32_t nOff = (uint32_t)(1 - buf) * 9216;
                cp_async16(xsBase + nOff + d0, gsrc + j0_ * ND + s0_ * 8);
                cp_async16(xsBase + nOff + d1, gsrc + j1_ * ND + s1_ * 8);
                cp_commit();
                cp_wait<1>();
            } else {
                cp_wait<0>();
            }
            __syncthreads();   // current chunk visible to all (also covers Wt)

            float acc[4][4] = {};
            #pragma unroll
            for (int ks = 0; ks < 4; ks++) {
                uint32_t a[4], b01[4], b23[4];
                ldsm_x4(a,   aAddr0 + bufOff + ks * 32);
                ldsm_x4(b01, bAddr1 + ks * 32);
                ldsm_x4(b23, bAddr2 + ks * 32);
                mma_bf16(acc[0], a, b01[0], b01[1]);
                mma_bf16(acc[1], a, b01[2], b01[3]);
                mma_bf16(acc[2], a, b23[0], b23[1]);
                mma_bf16(acc[3], a, b23[2], b23[3]);
            }

            float s0 = 0.f, s1 = 0.f;
            #pragma unroll
            for (int et = 0; et < 4; et++) {
                int e = eh + et * 8 + 2 * qc;
                s0 += aw_s[e]     * tanh_approx(acc[et][0] + ab_s[e]);
                s0 += aw_s[e + 1] * tanh_approx(acc[et][1] + ab_s[e + 1]);
                s1 += aw_s[e]     * tanh_approx(acc[et][2] + ab_s[e]);
                s1 += aw_s[e + 1] * tanh_approx(acc[et][3] + ab_s[e + 1]);
            }
            s0 += __shfl_xor_sync(0xffffffffu, s0, 1);
            s0 += __shfl_xor_sync(0xffffffffu, s0, 2);
            s1 += __shfl_xor_sync(0xffffffffu, s1, 1);
            s1 += __shfl_xor_sync(0xffffffffu, s1, 2);
            if (qc == 0) {
                spart[warp >> 2][jt + qr] = s0;
                spart[warp >> 2][jt + qr + 8] = s1;
            }
            __syncthreads();

            if (t < 64) {
                int j = jc * 64 + t;
                if (j >= i) {
                    float s = spart[0][t] + spart[1][t];
                    g_scores[(b * NN + i) * NN + j] = s;
                    g_scores[(b * NN + j) * NN + i] = s;
                }
            }
            __syncthreads();   // spart consumed; also guards next prefetch overwrite
        }
    }
}

// ---------------------------------------------------------------------------
// Phase 2 (round-14 exact kAgg v2): 8 rows/block, grid (64, NB).
// ---------------------------------------------------------------------------
__global__ __launch_bounds__(256) void kAgg(
    const float* __restrict__ x,
    const float* __restrict__ pw,
    const float* __restrict__ pwb,
    const float* __restrict__ pwo,
    const float* __restrict__ pwob)
{
    __shared__ uint32_t As[16][68];
    __shared__ __align__(16) uint32_t Xs[64][72];
    __shared__ float agg_s[8][64];
    __shared__ float Xi[8][64];
    __shared__ float hs[8][64];

    const int t = threadIdx.x;
    const int warp = t >> 5, lane = t & 31;
    const int qr = lane >> 2, qc = lane & 3;
    const int nt = warp;
    const int b = blockIdx.y;
    const int i0 = blockIdx.x * 8;
    const float* xb = x + b * NN * ND;

    for (int idx = t; idx < 8 * 64; idx += 256)
        As[8 + (idx >> 6)][idx & 63] = 0;
    for (int idx = t; idx < 8 * 64; idx += 256)
        Xi[idx >> 6][idx & 63] = xb[(i0 + (idx >> 6)) * ND + (idx & 63)];

    float sv[16];
    {
        const float* srow = g_scores + (b * NN + i0 + warp) * NN;
        float sum = 0.f;
        #pragma unroll
        for (int q = 0; q < 16; q++) {
            sv[q] = __expf(srow[q * 32 + lane] * TEMP_INV);
            sum += sv[q];
        }
        #pragma unroll
        for (int o = 16; o > 0; o >>= 1)
            sum += __shfl_xor_sync(0xffffffffu, sum, o);
        float inv = 1.f / sum;
        #pragma unroll
        for (int q = 0; q < 16; q++) sv[q] *= inv;
    }

    float acc[4] = {};
    #pragma unroll
    for (int jc = 0; jc < 8; jc++) {
        __syncthreads();
        As[warp][lane]      = to_tf32(sv[2 * jc]);
        As[warp][32 + lane] = to_tf32(sv[2 * jc + 1]);
        #pragma unroll
        for (int k = 0; k < 4; k++) {
            int v = t + k * 256;
            int j = v >> 4, d4 = v & 15;
            float4 f = *(const float4*)&xb[(jc * 64 + j) * ND + d4 * 4];
            uint4 u = { to_tf32(f.x), to_tf32(f.y), to_tf32(f.z), to_tf32(f.w) };
            *(uint4*)&Xs[j][d4 * 4] = u;
        }
        __syncthreads();

        #pragma unroll
        for (int ks = 0; ks < 8; ks++) {
            const int k0 = ks * 8;
            uint32_t a0 = As[qr][k0 + qc];
            uint32_t a1 = As[qr + 8][k0 + qc];
            uint32_t a2 = As[qr][k0 + qc + 4];
            uint32_t a3 = As[qr + 8][k0 + qc + 4];
            uint32_t b0 = Xs[k0 + qc][nt * 8 + qr];
            uint32_t b1 = Xs[k0 + qc + 4][nt * 8 + qr];
            mma_tf32(acc, a0, a1, a2, a3, b0, b1);
        }
    }

    agg_s[qr][nt * 8 + qc * 2]     = acc[0];
    agg_s[qr][nt * 8 + qc * 2 + 1] = acc[1];
    __syncthreads();

    {
        int e = t & 63, rg = t >> 6;
        float h0 = pwb[e] + pwob[e];
        float hv[2] = { h0, h0 };
        #pragma unroll 8
        for (int d = 0; d < 64; d++) {
            float pwv = pw[d * 64 + e];
            float pov = pwo[d * 64 + e];
            #pragma unroll
            for (int k = 0; k < 2; k++) {
                int rr = rg * 2 + k;
                hv[k] += agg_s[rr][d] * pwv + Xi[rr][d] * pov;
            }
        }
        #pragma unroll
        for (int k = 0; k < 2; k++) {
            int rr = rg * 2 + k;
            g_h[(b * NN + i0 + rr) * ND + e] = hv[k];
            hs[rr][e] = hv[k];
        }
    }
    __syncthreads();

    if (t < 128) {
        int f = t & 63;
        float s = 0.f;
        if (t < 64) {
            #pragma unroll
            for (int w = 0; w < 8; w++) s += hs[w][f];
        } else {
            #pragma unroll
            for (int w = 0; w < 8; w++) { float v = hs[w][f]; s += v * v; }
        }
        g_part[(b * 64 + blockIdx.x) * 128 + t] = s;
    }
}

// ---------------------------------------------------------------------------
// kTail v2 (round-14 exact): grid (8, NB), 256 threads, 64 rows per block.
// ---------------------------------------------------------------------------
__global__ __launch_bounds__(256) void kTail(
    const float* __restrict__ bn_g, const float* __restrict__ bn_b,
    const float* __restrict__ pool_w, const float* __restrict__ pool_b,
    float* __restrict__ out)
{
    __shared__ float red1[256], red2[256];
    __shared__ float a_s[64], c_s[64], pw_s[64];
    __shared__ float wv_s[512];
    __shared__ __align__(16) float hsel[64][68];
    __shared__ float rank_p[64][4];
    __shared__ int rank_s[64];

    const int t = threadIdx.x;
    const int b = blockIdx.y;
    const int i0 = blockIdx.x * 64;

    {
        int f = t & 63, grp = t >> 6;
        float s = 0.f, q = 0.f;
        #pragma unroll 8
        for (int blk = grp; blk < 128; blk += 4) {
            s += g_part[blk * 128 + f];
            q += g_part[blk * 128 + 64 + f];
        }
        red1[t] = s;
        red2[t] = q;
        __syncthreads();
        if (t < 64) {
            float S = red1[t] + red1[64 + t] + red1[128 + t] + red1[192 + t];
            float Q = red2[t] + red2[64 + t] + red2[128 + t] + red2[192 + t];
            float mean = S * (1.f / (NB * NN));
            float var = fmaxf(Q * (1.f / (NB * NN)) - mean * mean, 0.f);
            float a = rsqrtf(var + BN_EPS) * bn_g[t];
            a_s[t] = a;
            c_s[t] = bn_b[t] - mean * a;
            pw_s[t] = pool_w[t];
        }
        __syncthreads();
    }

    const float pb = pool_b[0];

    #pragma unroll
    for (int half = 0; half < 2; half++) {
        int r = t + half * 256;
        const float* hr = g_h + (b * NN + r) * ND;
        bool own = (unsigned)(r - i0) < 64u;
        float p = 0.f;
        #pragma unroll
        for (int q = 0; q < 16; q++) {
            float4 v = *(const float4*)&hr[q * 4];
            float4 o;
            {
                int e = q * 4;
                float hn = v.x * a_s[e] + c_s[e];
                o.x = hn > 0.f ? SELU_SCALE * hn
                               : SELU_SCALE * SELU_ALPHA * (__expf(hn) - 1.f);
                p += o.x * pw_s[e];
                hn = v.y * a_s[e + 1] + c_s[e + 1];
                o.y = hn > 0.f ? SELU_SCALE * hn
                               : SELU_SCALE * SELU_ALPHA * (__expf(hn) - 1.f);
                p += o.y * pw_s[e + 1];
                hn = v.z * a_s[e + 2] + c_s[e + 2];
                o.z = hn > 0.f ? SELU_SCALE * hn
                               : SELU_SCALE * SELU_ALPHA * (__expf(hn) - 1.f);
                p += o.z * pw_s[e + 2];
                hn = v.w * a_s[e + 3] + c_s[e + 3];
                o.w = hn > 0.f ? SELU_SCALE * hn
                               : SELU_SCALE * SELU_ALPHA * (__expf(hn) - 1.f);
                p += o.w * pw_s[e + 3];
            }
            if (own) *(float4*)&hsel[r - i0][q * 4] = o;
        }
        wv_s[r] = 1.f / (1.f + __expf(-(p + pb)));
    }
    __syncthreads();

    {
        int lr = t & 63, seg = t >> 6;
        int row = i0 + lr;
        float w = wv_s[row];
        int pr = 0;
        #pragma unroll 8
        for (int j = seg * 128; j < seg * 128 + 128; j++) {
            float u = wv_s[j];
            pr += (u > w) || (u == w && j < row);
        }
        rank_p[lr][seg] = (float)pr;
    }
    __syncthreads();
    if (t < 64)
        rank_s[t] = (int)(rank_p[t][0] + rank_p[t][1] + rank_p[t][2] + rank_p[t][3]);
    __syncthreads();

    {
        int lr = t >> 2, part = t & 3;
        int rk = rank_s[lr];
        if (rk < KN) {
            float w = wv_s[i0 + lr];
            float* dp = out + (b * KN + rk) * ND + part * 16;
            #pragma unroll
            for (int q = 0; q < 4; q++) {
                float4 o = *(float4*)&hsel[lr][part * 16 + q * 4];
                o.x *= w; o.y *= w; o.z *= w; o.w *= w;
                *(float4*)&dp[q * 4] = o;
            }
        }
    }
}

// ---------------------------------------------------------------------------
// Launch (graph-capturable): 4 kernels.
// ---------------------------------------------------------------------------
extern "C" void kernel_launch(void* const* d_in, const int* in_sizes, int n_in,
                              void* d_out, int out_size)
{
    const float* x     = (const float*)d_in[0];
    const float* apw   = (const float*)d_in[1];
    const float* apb   = (const float*)d_in[2];
    const float* awt   = (const float*)d_in[3];
    const float* pw    = (const float*)d_in[4];
    const float* pwb   = (const float*)d_in[5];
    const float* pwo   = (const float*)d_in[6];
    const float* pwob  = (const float*)d_in[7];
    const float* bn_g  = (const float*)d_in[8];
    const float* bn_b  = (const float*)d_in[9];
    const float* poolw = (const float*)d_in[10];
    const float* poolb = (const float*)d_in[11];
    float* out = (float*)d_out;

    kPrep<<<64, 256>>>(x);
    kScores<<<dim3(NN / 2, NB), 256>>>(x, apw, apb, awt);
    kAgg<<<dim3(NN / 8, NB), 256>>>(x, pw, pwb, pwo, pwob);
    kTail<<<dim3(8, NB), 256>>>(bn_g, bn_b, poolw, poolb, out);
}

// round 17
// speedup vs baseline: 1.5691x; 1.2838x over previous
#include <cuda_runtime.h>
#include <cuda_bf16.h>
#include <cstdint>

// ---------------------------------------------------------------------------
// B=2, N=512, D_IN=D_OUT=64, TEMP=100, POOL_K=0.5 -> kn=256
// ---------------------------------------------------------------------------
#define NB 2
#define NN 512
#define ND 64
#define KN 256
#define TEMP_INV (1.0f/100.0f)
#define BN_EPS 1e-5f
#define SELU_SCALE 1.0507009873554804934193349852946f
#define SELU_ALPHA 1.6732632423543772848170429916717f

__device__ float g_scores[NB*NN*NN];
__device__ float g_h[NB*NN*ND];
__device__ float g_part[128*128];            // per-kAgg-block partial BN stats
__device__ __nv_bfloat16 g_xbf[NB*NN*ND];    // bf16 copy of x (kPrep)
__device__ float g_hsel[NB*NN*ND];           // selu(bn(h)) per row
__device__ float g_w[NB*NN];                 // pool gate per row

__device__ __forceinline__ float tanh_approx(float x) {
    float r;
    asm("tanh.approx.f32 %0, %1;" : "=f"(r) : "f"(x));
    return r;
}
__device__ __forceinline__ uint32_t to_tf32(float f) {
    uint32_t u;
    asm("cvt.rna.tf32.f32 %0, %1;" : "=r"(u) : "f"(f));
    return u;
}
__device__ __forceinline__ void mma_tf32(float c[4], uint32_t a0, uint32_t a1,
                                         uint32_t a2, uint32_t a3,
                                         uint32_t b0, uint32_t b1) {
    asm("mma.sync.aligned.m16n8k8.row.col.f32.tf32.tf32.f32 "
        "{%0,%1,%2,%3}, {%4,%5,%6,%7}, {%8,%9}, {%0,%1,%2,%3};"
        : "+f"(c[0]), "+f"(c[1]), "+f"(c[2]), "+f"(c[3])
        : "r"(a0), "r"(a1), "r"(a2), "r"(a3), "r"(b0), "r"(b1));
}
__device__ __forceinline__ void mma_bf16(float c[4], const uint32_t a[4],
                                         uint32_t b0, uint32_t b1) {
    asm("mma.sync.aligned.m16n8k16.row.col.f32.bf16.bf16.f32 "
        "{%0,%1,%2,%3}, {%4,%5,%6,%7}, {%8,%9}, {%0,%1,%2,%3};"
        : "+f"(c[0]), "+f"(c[1]), "+f"(c[2]), "+f"(c[3])
        : "r"(a[0]), "r"(a[1]), "r"(a[2]), "r"(a[3]), "r"(b0), "r"(b1));
}
__device__ __forceinline__ void ldsm_x4(uint32_t r[4], uint32_t addr) {
    asm volatile("ldmatrix.sync.aligned.m8n8.x4.shared.b16 {%0,%1,%2,%3}, [%4];"
        : "=r"(r[0]), "=r"(r[1]), "=r"(r[2]), "=r"(r[3]) : "r"(addr));
}
__device__ __forceinline__ void cp_async16(uint32_t smem, const void* g) {
    asm volatile("cp.async.cg.shared.global [%0], [%1], 16;"
        :: "r"(smem), "l"(g));
}
__device__ __forceinline__ void cp_commit() {
    asm volatile("cp.async.commit_group;");
}
template <int N>
__device__ __forceinline__ void cp_wait() {
    asm volatile("cp.async.wait_group %0;" :: "n"(N));
}

// ---------------------------------------------------------------------------
// kPrep: x (f32) -> g_xbf (bf16), once.
// ---------------------------------------------------------------------------
__global__ __launch_bounds__(256) void kPrep(const float* __restrict__ x) {
    int idx = blockIdx.x * 256 + threadIdx.x;    // 0..16383
    float4 f = ((const float4*)x)[idx];
    __nv_bfloat162 lo = __float22bfloat162_rn(make_float2(f.x, f.y));
    __nv_bfloat162 hi = __float22bfloat162_rn(make_float2(f.z, f.w));
    uint2 u = { *(uint32_t*)&lo, *(uint32_t*)&hi };
    *(uint2*)&g_xbf[idx * 4] = u;
}

// ---------------------------------------------------------------------------
// Phase 1 v3 (round-16 exact): bf16 MMA + ldmatrix + cp.async double buffer.
// ---------------------------------------------------------------------------
__global__ __launch_bounds__(256) void kScores(
    const float* __restrict__ x,
    const float* __restrict__ apw,
    const float* __restrict__ apb,
    const float* __restrict__ awt)
{
    __shared__ __align__(16) __nv_bfloat16 Xs[2][64][72];  // double buffer
    __shared__ __align__(16) __nv_bfloat16 Wt[64][72];     // [e][d]
    __shared__ float spart[2][64];
    __shared__ float xi_s[64], ab_s[64], aw_s[64];

    const int t = threadIdx.x;
    const int p = blockIdx.x;
    const int b = blockIdx.y;
    const float* xb = x + b * NN * ND;
    const __nv_bfloat16* xbfb = g_xbf + b * NN * ND;

    const int warp = t >> 5, lane = t & 31;
    const int jt = (warp & 3) * 16;
    const int eh = (warp >> 2) * 32;
    const int qr = lane >> 2, qc = lane & 3;

    if (t < 64) { ab_s[t] = apb[t]; aw_s[t] = awt[t]; }

    const uint32_t xsBase = (uint32_t)__cvta_generic_to_shared(&Xs[0][0][0]);
    const uint32_t wtBase = (uint32_t)__cvta_generic_to_shared(&Wt[0][0]);
    const uint32_t aAddr0 = xsBase + (jt + (lane & 15)) * 144 + (lane >> 4) * 16;
    const uint32_t bAddr1 = wtBase +
        (eh + (lane >> 4) * 8 + (lane & 7)) * 144 + ((lane >> 3) & 1) * 16;
    const uint32_t bAddr2 = bAddr1 + 16 * 144;

    const int j0_ = t >> 3, s0_ = t & 7;
    const int j1_ = (t + 256) >> 3, s1_ = t & 7;
    const uint32_t d0 = j0_ * 144 + s0_ * 16;
    const uint32_t d1 = j1_ * 144 + s1_ * 16;

    #pragma unroll 1
    for (int r = 0; r < 2; r++) {
        const int i = r ? (NN - 1 - p) : p;
        __syncthreads();
        if (t < 64) xi_s[t] = xb[i * ND + t];
        __syncthreads();

        #pragma unroll
        for (int k = 0; k < 16; k++) {
            int idx = t + k * 256;
            int d = idx >> 6, e = idx & 63;
            Wt[e][d] = __float2bfloat16(xi_s[d] * apw[idx]);
        }

        const int jc0 = i >> 6;
        {
            const __nv_bfloat16* gsrc = xbfb + jc0 * 64 * ND;
            cp_async16(xsBase + d0, gsrc + j0_ * ND + s0_ * 8);
            cp_async16(xsBase + d1, gsrc + j1_ * ND + s1_ * 8);
            cp_commit();
        }

        for (int jc = jc0; jc < 8; jc++) {
            const int buf = (jc - jc0) & 1;
            const uint32_t bufOff = (uint32_t)buf * 9216;
            if (jc < 7) {
                const __nv_bfloat16* gsrc = xbfb + (jc + 1) * 64 * ND;
                const uint32_t nOff = (uint32_t)(1 - buf) * 9216;
                cp_async16(xsBase + nOff + d0, gsrc + j0_ * ND + s0_ * 8);
                cp_async16(xsBase + nOff + d1, gsrc + j1_ * ND + s1_ * 8);
                cp_commit();
                cp_wait<1>();
            } else {
                cp_wait<0>();
            }
            __syncthreads();

            float acc[4][4] = {};
            #pragma unroll
            for (int ks = 0; ks < 4; ks++) {
                uint32_t a[4], b01[4], b23[4];
                ldsm_x4(a,   aAddr0 + bufOff + ks * 32);
                ldsm_x4(b01, bAddr1 + ks * 32);
                ldsm_x4(b23, bAddr2 + ks * 32);
                mma_bf16(acc[0], a, b01[0], b01[1]);
                mma_bf16(acc[1], a, b01[2], b01[3]);
                mma_bf16(acc[2], a, b23[0], b23[1]);
                mma_bf16(acc[3], a, b23[2], b23[3]);
            }

            float s0 = 0.f, s1 = 0.f;
            #pragma unroll
            for (int et = 0; et < 4; et++) {
                int e = eh + et * 8 + 2 * qc;
                s0 += aw_s[e]     * tanh_approx(acc[et][0] + ab_s[e]);
                s0 += aw_s[e + 1] * tanh_approx(acc[et][1] + ab_s[e + 1]);
                s1 += aw_s[e]     * tanh_approx(acc[et][2] + ab_s[e]);
                s1 += aw_s[e + 1] * tanh_approx(acc[et][3] + ab_s[e + 1]);
            }
            s0 += __shfl_xor_sync(0xffffffffu, s0, 1);
            s0 += __shfl_xor_sync(0xffffffffu, s0, 2);
            s1 += __shfl_xor_sync(0xffffffffu, s1, 1);
            s1 += __shfl_xor_sync(0xffffffffu, s1, 2);
            if (qc == 0) {
                spart[warp >> 2][jt + qr] = s0;
                spart[warp >> 2][jt + qr + 8] = s1;
            }
            __syncthreads();

            if (t < 64) {
                int j = jc * 64 + t;
                if (j >= i) {
                    float s = spart[0][t] + spart[1][t];
                    g_scores[(b * NN + i) * NN + j] = s;
                    g_scores[(b * NN + j) * NN + i] = s;
                }
            }
            __syncthreads();
        }
    }
}

// ---------------------------------------------------------------------------
// Phase 2 (round-14 exact kAgg v2): 8 rows/block, grid (64, NB).
// ---------------------------------------------------------------------------
__global__ __launch_bounds__(256) void kAgg(
    const float* __restrict__ x,
    const float* __restrict__ pw,
    const float* __restrict__ pwb,
    const float* __restrict__ pwo,
    const float* __restrict__ pwob)
{
    __shared__ uint32_t As[16][68];
    __shared__ __align__(16) uint32_t Xs[64][72];
    __shared__ float agg_s[8][64];
    __shared__ float Xi[8][64];
    __shared__ float hs[8][64];

    const int t = threadIdx.x;
    const int warp = t >> 5, lane = t & 31;
    const int qr = lane >> 2, qc = lane & 3;
    const int nt = warp;
    const int b = blockIdx.y;
    const int i0 = blockIdx.x * 8;
    const float* xb = x + b * NN * ND;

    for (int idx = t; idx < 8 * 64; idx += 256)
        As[8 + (idx >> 6)][idx & 63] = 0;
    for (int idx = t; idx < 8 * 64; idx += 256)
        Xi[idx >> 6][idx & 63] = xb[(i0 + (idx >> 6)) * ND + (idx & 63)];

    float sv[16];
    {
        const float* srow = g_scores + (b * NN + i0 + warp) * NN;
        float sum = 0.f;
        #pragma unroll
        for (int q = 0; q < 16; q++) {
            sv[q] = __expf(srow[q * 32 + lane] * TEMP_INV);
            sum += sv[q];
        }
        #pragma unroll
        for (int o = 16; o > 0; o >>= 1)
            sum += __shfl_xor_sync(0xffffffffu, sum, o);
        float inv = 1.f / sum;
        #pragma unroll
        for (int q = 0; q < 16; q++) sv[q] *= inv;
    }

    float acc[4] = {};
    #pragma unroll
    for (int jc = 0; jc < 8; jc++) {
        __syncthreads();
        As[warp][lane]      = to_tf32(sv[2 * jc]);
        As[warp][32 + lane] = to_tf32(sv[2 * jc + 1]);
        #pragma unroll
        for (int k = 0; k < 4; k++) {
            int v = t + k * 256;
            int j = v >> 4, d4 = v & 15;
            float4 f = *(const float4*)&xb[(jc * 64 + j) * ND + d4 * 4];
            uint4 u = { to_tf32(f.x), to_tf32(f.y), to_tf32(f.z), to_tf32(f.w) };
            *(uint4*)&Xs[j][d4 * 4] = u;
        }
        __syncthreads();

        #pragma unroll
        for (int ks = 0; ks < 8; ks++) {
            const int k0 = ks * 8;
            uint32_t a0 = As[qr][k0 + qc];
            uint32_t a1 = As[qr + 8][k0 + qc];
            uint32_t a2 = As[qr][k0 + qc + 4];
            uint32_t a3 = As[qr + 8][k0 + qc + 4];
            uint32_t b0 = Xs[k0 + qc][nt * 8 + qr];
            uint32_t b1 = Xs[k0 + qc + 4][nt * 8 + qr];
            mma_tf32(acc, a0, a1, a2, a3, b0, b1);
        }
    }

    agg_s[qr][nt * 8 + qc * 2]     = acc[0];
    agg_s[qr][nt * 8 + qc * 2 + 1] = acc[1];
    __syncthreads();

    {
        int e = t & 63, rg = t >> 6;
        float h0 = pwb[e] + pwob[e];
        float hv[2] = { h0, h0 };
        #pragma unroll 8
        for (int d = 0; d < 64; d++) {
            float pwv = pw[d * 64 + e];
            float pov = pwo[d * 64 + e];
            #pragma unroll
            for (int k = 0; k < 2; k++) {
                int rr = rg * 2 + k;
                hv[k] += agg_s[rr][d] * pwv + Xi[rr][d] * pov;
            }
        }
        #pragma unroll
        for (int k = 0; k < 2; k++) {
            int rr = rg * 2 + k;
            g_h[(b * NN + i0 + rr) * ND + e] = hv[k];
            hs[rr][e] = hv[k];
        }
    }
    __syncthreads();

    if (t < 128) {
        int f = t & 63;
        float s = 0.f;
        if (t < 64) {
            #pragma unroll
            for (int w = 0; w < 8; w++) s += hs[w][f];
        } else {
            #pragma unroll
            for (int w = 0; w < 8; w++) { float v = hs[w][f]; s += v * v; }
        }
        g_part[(b * 64 + blockIdx.x) * 128 + t] = s;
    }
}

// ---------------------------------------------------------------------------
// kGate: grid (64, NB) = 128 blocks, 8 rows/block (warp per row).
// Redundant (cheap) stats reduce; each row's BN+SELU+pool gate computed ONCE.
// selu -> g_hsel, gate -> g_w.
// ---------------------------------------------------------------------------
__global__ __launch_bounds__(256) void kGate(
    const float* __restrict__ bn_g, const float* __restrict__ bn_b,
    const float* __restrict__ pool_w, const float* __restrict__ pool_b)
{
    __shared__ float red1[256], red2[256];
    __shared__ float a_s[64], c_s[64], pw_s[64];

    const int t = threadIdx.x;
    const int warp = t >> 5, lane = t & 31;
    const int b = blockIdx.y;
    const int row = blockIdx.x * 8 + warp;

    // stats reduce (redundant per block; deterministic)
    {
        int f = t & 63, grp = t >> 6;
        float s = 0.f, q = 0.f;
        #pragma unroll 8
        for (int blk = grp; blk < 128; blk += 4) {
            s += g_part[blk * 128 + f];
            q += g_part[blk * 128 + 64 + f];
        }
        red1[t] = s;
        red2[t] = q;
        __syncthreads();
        if (t < 64) {
            float S = red1[t] + red1[64 + t] + red1[128 + t] + red1[192 + t];
            float Q = red2[t] + red2[64 + t] + red2[128 + t] + red2[192 + t];
            float mean = S * (1.f / (NB * NN));
            float var = fmaxf(Q * (1.f / (NB * NN)) - mean * mean, 0.f);
            float a = rsqrtf(var + BN_EPS) * bn_g[t];
            a_s[t] = a;
            c_s[t] = bn_b[t] - mean * a;
            pw_s[t] = pool_w[t];
        }
        __syncthreads();
    }

    // gate: warp per row, lane owns features 2*lane, 2*lane+1
    const float* hr = g_h + (b * NN + row) * ND;
    int e0 = lane * 2;
    float2 v = *(const float2*)&hr[e0];
    float hn0 = v.x * a_s[e0] + c_s[e0];
    float s0 = hn0 > 0.f ? SELU_SCALE * hn0
                         : SELU_SCALE * SELU_ALPHA * (__expf(hn0) - 1.f);
    float hn1 = v.y * a_s[e0 + 1] + c_s[e0 + 1];
    float s1 = hn1 > 0.f ? SELU_SCALE * hn1
                         : SELU_SCALE * SELU_ALPHA * (__expf(hn1) - 1.f);
    float p = s0 * pw_s[e0] + s1 * pw_s[e0 + 1];
    #pragma unroll
    for (int o = 16; o > 0; o >>= 1)
        p += __shfl_xor_sync(0xffffffffu, p, o);
    float w = 1.f / (1.f + __expf(-(p + pool_b[0])));

    float2 sv = { s0, s1 };
    *(float2*)&g_hsel[(b * NN + row) * ND + e0] = sv;
    if (lane == 0) g_w[b * NN + row] = w;
}

// ---------------------------------------------------------------------------
// kRank: grid (8, NB), 256 threads, 64 rows/block.
// Rank (value desc, index asc) with 4 threads/row; scatter hsel*w to out.
// ---------------------------------------------------------------------------
__global__ __launch_bounds__(256) void kRank(float* __restrict__ out) {
    __shared__ float wv_s[512];
    __shared__ float rank_p[64][4];
    __shared__ int rank_s[64];

    const int t = threadIdx.x;
    const int b = blockIdx.y;
    const int i0 = blockIdx.x * 64;

    wv_s[t] = g_w[b * NN + t];
    wv_s[t + 256] = g_w[b * NN + t + 256];
    __syncthreads();

    {
        int lr = t & 63, seg = t >> 6;
        int row = i0 + lr;
        float w = wv_s[row];
        int pr = 0;
        #pragma unroll 8
        for (int j = seg * 128; j < seg * 128 + 128; j++) {
            float u = wv_s[j];
            pr += (u > w) || (u == w && j < row);
        }
        rank_p[lr][seg] = (float)pr;
    }
    __syncthreads();
    if (t < 64)
        rank_s[t] = (int)(rank_p[t][0] + rank_p[t][1] + rank_p[t][2] + rank_p[t][3]);
    __syncthreads();

    {
        int lr = t >> 2, part = t & 3;
        int rk = rank_s[lr];
        if (rk < KN) {
            float w = wv_s[i0 + lr];
            const float* sp = g_hsel + (b * NN + i0 + lr) * ND + part * 16;
            float* dp = out + (b * KN + rk) * ND + part * 16;
            #pragma unroll
            for (int q = 0; q < 4; q++) {
                float4 o = *(const float4*)&sp[q * 4];
                o.x *= w; o.y *= w; o.z *= w; o.w *= w;
                *(float4*)&dp[q * 4] = o;
            }
        }
    }
}

// ---------------------------------------------------------------------------
// Launch (graph-capturable): 5 kernels.
// ---------------------------------------------------------------------------
extern "C" void kernel_launch(void* const* d_in, const int* in_sizes, int n_in,
                              void* d_out, int out_size)
{
    const float* x     = (const float*)d_in[0];
    const float* apw   = (const float*)d_in[1];
    const float* apb   = (const float*)d_in[2];
    const float* awt   = (const float*)d_in[3];
    const float* pw    = (const float*)d_in[4];
    const float* pwb   = (const float*)d_in[5];
    const float* pwo   = (const float*)d_in[6];
    const float* pwob  = (const float*)d_in[7];
    const float* bn_g  = (const float*)d_in[8];
    const float* bn_b  = (const float*)d_in[9];
    const float* poolw = (const float*)d_in[10];
    const float* poolb = (const float*)d_in[11];
    float* out = (float*)d_out;

    kPrep<<<64, 256>>>(x);
    kScores<<<dim3(NN / 2, NB), 256>>>(x, apw, apb, awt);
    kAgg<<<dim3(NN / 8, NB), 256>>>(x, pw, pwb, pwo, pwob);
    kGate<<<dim3(64, NB), 256>>>(bn_g, bn_b, poolw, poolb);
    kRank<<<dim3(8, NB), 256>>>(out);
}